// round 6
// baseline (speedup 1.0000x reference)
#include <cuda_runtime.h>
#include <cuda_fp16.h>
#include <cstdint>

// Correlation layer via band-restricted mma.sync (m16n8k16 fp16, fp32 accum).
// out[b, di*9+dj, h, w] = sum_c f1[b,c,h,w] * f2[b,c,h+di-4,w+dj-4]
// B=8, C=256, H=64, W=128, D=81.
//
// R6: no-halo layout (out-of-range band cols are exactly 0 by zero-padding ->
//     write 0 in epilogue), all-16B cp.async, 4-deep pipeline with one
//     __syncthreads per chunk, 4-tile band per warp via 2x ldmatrix.x4.

#define NB 8
#define NC 256
#define NH 64
#define NW 128
#define ND 81

#define RSTRIDE 272                 // bytes per c-row (256 data + 16 pad); 272%128==16 -> LDSM conflict-free
#define F2ROW (16 * RSTRIDE)        // one f2 row-block (16 c) = 4352 B
#define OFF_F1 (9 * F2ROW)          // 39168
#define BUFSZ (OFF_F1 + F2ROW)      // 43520 B per pipeline buffer
#define NBUF 4
#define OFF_STAGE (NBUF * BUFSZ)    // 174080
#define STAGE_W 33                  // floats per staging row (32 band cols + pad)
#define SMEM_SZ (OFF_STAGE + 8 * 16 * STAGE_W * 4)   // 190976 B

__device__ __half g_f1h[(size_t)NB * NC * NH * NW];
__device__ __half g_f2h[(size_t)NB * NC * NH * NW];

// ---------------- fp32 -> fp16 cast (layout-preserving) ----------------
__global__ void cast_kernel(const float4* __restrict__ f1,
                            const float4* __restrict__ f2) {
    const float4* src = blockIdx.y ? f2 : f1;
    __half* dst = blockIdx.y ? g_f2h : g_f1h;
    size_t i0 = (size_t)blockIdx.x * 1024 + threadIdx.x;
    #pragma unroll
    for (int k = 0; k < 4; k++) {
        size_t i = i0 + 256 * k;
        float4 v = src[i];
        __half2 h0 = __floats2half2_rn(v.x, v.y);
        __half2 h1 = __floats2half2_rn(v.z, v.w);
        uint2 o;
        o.x = *reinterpret_cast<uint32_t*>(&h0);
        o.y = *reinterpret_cast<uint32_t*>(&h1);
        reinterpret_cast<uint2*>(dst)[i] = o;
    }
}

// ---------------- PTX helpers ----------------
__device__ __forceinline__ void cpa16(uint32_t dst, const void* src) {
    asm volatile("cp.async.ca.shared.global [%0], [%1], 16;" :: "r"(dst), "l"(src));
}
__device__ __forceinline__ void ldsm4t(uint32_t& r0, uint32_t& r1,
                                       uint32_t& r2, uint32_t& r3, uint32_t a) {
    asm volatile("ldmatrix.sync.aligned.m8n8.x4.trans.shared.b16 {%0,%1,%2,%3}, [%4];"
                 : "=r"(r0), "=r"(r1), "=r"(r2), "=r"(r3) : "r"(a));
}
__device__ __forceinline__ void ldsm2t(uint32_t& r0, uint32_t& r1, uint32_t a) {
    asm volatile("ldmatrix.sync.aligned.m8n8.x2.trans.shared.b16 {%0,%1}, [%2];"
                 : "=r"(r0), "=r"(r1) : "r"(a));
}
__device__ __forceinline__ void mma16816(float* d, uint32_t a0, uint32_t a1,
                                         uint32_t a2, uint32_t a3,
                                         uint32_t b0, uint32_t b1) {
    asm volatile("mma.sync.aligned.m16n8k16.row.col.f32.f16.f16.f32 "
                 "{%0,%1,%2,%3}, {%4,%5,%6,%7}, {%8,%9}, {%0,%1,%2,%3};"
                 : "+f"(d[0]), "+f"(d[1]), "+f"(d[2]), "+f"(d[3])
                 : "r"(a0), "r"(a1), "r"(a2), "r"(a3), "r"(b0), "r"(b1));
}

// ---------------- main kernel ----------------
__global__ void __launch_bounds__(256, 1)
corr_mma(float* __restrict__ out) {
    extern __shared__ char smem[];
    const uint32_t sb = (uint32_t)__cvta_generic_to_shared(smem);
    const int tid = threadIdx.x;
    const int lane = tid & 31, warp = tid >> 5;   // warp = m16 block over w
    const int h = blockIdx.x, b = blockIdx.y;
    const size_t bbase = (size_t)b * NC * NH * NW;

    float acc[9][4][4];
    #pragma unroll
    for (int r = 0; r < 9; r++)
        #pragma unroll
        for (int t = 0; t < 4; t++)
            #pragma unroll
            for (int k = 0; k < 4; k++)
                acc[r][t][k] = 0.0f;

    // ldmatrix per-lane address components.
    // A (f1, [c][w], .trans): quads (m0-7,k0-7),(m8-15,k0-7),(m0-7,k8-15),(m8-15,k8-15)
    const int q = lane >> 3, lrow = lane & 7;
    const uint32_t a_off = OFF_F1 + (uint32_t)(lrow + ((q >> 1) << 3)) * RSTRIDE
                         + ((16 * warp + ((q & 1) << 3)) << 1);
    // B (f2, [c][w], .trans, x4): lanes 0-15 -> k rows of n-block, 16-31 -> n-block+8
    const uint32_t b_off = (uint32_t)(lane & 15) * RSTRIDE + ((lane >> 4) << 4);

    // Band tiles for warp m start at col tb = 16m-8 (tile t at col tb+8t).
    const int tb = 16 * warp - 8;
    const bool has_t0 = (warp > 0), has_t3 = (warp < 7);

    // cp.async: per chunk, thread (ci, sg) copies one 16B seg of each of the
    // 9 f2 rows + the f1 row. All 16B, no halo.
    const int ci = tid >> 4, sg = tid & 15;
    auto issue = [&](int cc) {
        const int c0 = cc * 16;
        const uint32_t dbase = sb + (cc & (NBUF - 1)) * BUFSZ;
        const uint32_t doff = ci * RSTRIDE + 16 * sg;
        #pragma unroll
        for (int r = 0; r < 9; r++) {
            int gr = h + r - 4;
            gr = gr < 0 ? 0 : (gr > NH - 1 ? NH - 1 : gr);  // clamp; invalid di -> epilogue zeros
            const __half* src = g_f2h + bbase + ((size_t)(c0 + ci) * NH + gr) * NW + 8 * sg;
            cpa16(dbase + r * F2ROW + doff, src);
        }
        const __half* s1 = g_f1h + bbase + ((size_t)(c0 + ci) * NH + h) * NW + 8 * sg;
        cpa16(dbase + OFF_F1 + doff, s1);
    };

    // prologue: 3 chunks in flight
    #pragma unroll
    for (int p = 0; p < 3; p++) {
        issue(p);
        asm volatile("cp.async.commit_group;");
    }

    for (int cc = 0; cc < 16; cc++) {
        // commits before this wait = 3 + cc; keep newest 2 pending -> chunk cc done
        asm volatile("cp.async.wait_group 2;");
        __syncthreads();
        if (cc + 3 < 16) issue(cc + 3);          // buf (cc-1)%4: consumers done (barrier above)
        asm volatile("cp.async.commit_group;");  // empty at tail keeps count uniform

        const uint32_t base = sb + (cc & (NBUF - 1)) * BUFSZ;
        uint32_t a0, a1, a2, a3;
        ldsm4t(a0, a1, a2, a3, base + a_off);
        #pragma unroll
        for (int r = 0; r < 9; r++) {
            const uint32_t brow = base + r * F2ROW + b_off;
            uint32_t bq[8];
            if (has_t0) ldsm4t(bq[0], bq[1], bq[2], bq[3], brow + 2 * tb);
            else        ldsm2t(bq[2], bq[3], brow + 0);            // t1 at col 0
            if (has_t3) ldsm4t(bq[4], bq[5], bq[6], bq[7], brow + 2 * tb + 32);
            else        ldsm2t(bq[4], bq[5], brow + 2 * tb + 32);  // t2 at col 120
            if (has_t0) mma16816(acc[r][0], a0, a1, a2, a3, bq[0], bq[1]);
            mma16816(acc[r][1], a0, a1, a2, a3, bq[2], bq[3]);
            mma16816(acc[r][2], a0, a1, a2, a3, bq[4], bq[5]);
            if (has_t3) mma16816(acc[r][3], a0, a1, a2, a3, bq[6], bq[7]);
        }
    }

    // ---------------- epilogue: band extraction via per-warp staging ----------------
    float* stage = reinterpret_cast<float*>(smem + OFF_STAGE) + warp * 16 * STAGE_W;
    const int gid = lane >> 2, tig = lane & 3;
    const int l16 = lane & 15, dh = lane >> 4;
    #pragma unroll
    for (int r = 0; r < 9; r++) {
        #pragma unroll
        for (int t = 0; t < 4; t++) {
            stage[gid * STAGE_W + 8 * t + 2 * tig]           = acc[r][t][0];
            stage[gid * STAGE_W + 8 * t + 2 * tig + 1]       = acc[r][t][1];
            stage[(gid + 8) * STAGE_W + 8 * t + 2 * tig]     = acc[r][t][2];
            stage[(gid + 8) * STAGE_W + 8 * t + 2 * tig + 1] = acc[r][t][3];
        }
        __syncwarp();
        const int gr = h + r - 4;
        const bool rowok = (gr >= 0 && gr < NH);
        const int w = 16 * warp + l16;
        // local band col for (w, dj): (w + dj - 4) - tb = l16 + dj + 4
        #pragma unroll
        for (int rd = 0; rd < 5; rd++) {
            int dj = 2 * rd + dh;
            if (dj < 9) {
                int bc = w + dj - 4;
                float v = (rowok && bc >= 0 && bc < NW)
                            ? stage[l16 * STAGE_W + l16 + dj + 4] : 0.0f;
                out[(((size_t)b * ND + r * 9 + dj) * NH + h) * NW + w] = v;
            }
        }
        __syncwarp();
    }
}

extern "C" void kernel_launch(void* const* d_in, const int* in_sizes, int n_in,
                              void* d_out, int out_size) {
    const float* f1 = (const float*)d_in[0];
    const float* f2 = (const float*)d_in[1];
    float* out = (float*)d_out;

    cudaFuncSetAttribute(corr_mma, cudaFuncAttributeMaxDynamicSharedMemorySize, SMEM_SZ);

    cast_kernel<<<dim3(4096, 2), 256>>>((const float4*)f1, (const float4*)f2);
    corr_mma<<<dim3(NH, NB), 256, SMEM_SZ>>>(out);
}

// round 7
// speedup vs baseline: 1.1285x; 1.1285x over previous
#include <cuda_runtime.h>
#include <cuda_fp16.h>
#include <cstdint>

// Correlation layer via band-restricted mma.sync (m16n8k16 fp16, fp32 accum).
// out[b, di*9+dj, h, w] = sum_c f1[b,c,h,w] * f2[b,c,h+di-4,w+dj-4]
// B=8, C=256, H=64, W=128, D=81.
//
// R7 = R5 compute structure (3-tile band, halo layout, 108 acc regs)
//      + depth-4 cp.async ring with a single __syncthreads per chunk.

#define NB 8
#define NC 256
#define NH 64
#define NW 128
#define ND 81

#define RSTRIDE 272                 // bytes per c-row (136 halves; 272%128==16 -> LDSM conflict-free)
#define F2ROW (16 * RSTRIDE)        // one f2 row-block (16 c) = 4352 B
#define OFF_F1 (9 * F2ROW)          // 39168
#define BUFSZ (OFF_F1 + F2ROW)      // 43520 B per pipeline buffer
#define NBUF 4
#define OFF_STAGE (NBUF * BUFSZ)    // 174080
#define STAGE_W 25                  // floats per staging row (16 rows/warp)
#define SMEM_SZ (OFF_STAGE + 8 * 16 * STAGE_W * 4)   // 186880 B

__device__ __half g_f1h[(size_t)NB * NC * NH * NW];
__device__ __half g_f2h[(size_t)NB * NC * NH * NW];

// ---------------- fp32 -> fp16 cast (layout-preserving) ----------------
__global__ void cast_kernel(const float4* __restrict__ f1,
                            const float4* __restrict__ f2) {
    const float4* src = blockIdx.y ? f2 : f1;
    __half* dst = blockIdx.y ? g_f2h : g_f1h;
    size_t i0 = (size_t)blockIdx.x * 1024 + threadIdx.x;
    #pragma unroll
    for (int k = 0; k < 4; k++) {
        size_t i = i0 + 256 * k;
        float4 v = src[i];
        __half2 h0 = __floats2half2_rn(v.x, v.y);
        __half2 h1 = __floats2half2_rn(v.z, v.w);
        uint2 o;
        o.x = *reinterpret_cast<uint32_t*>(&h0);
        o.y = *reinterpret_cast<uint32_t*>(&h1);
        reinterpret_cast<uint2*>(dst)[i] = o;
    }
}

// ---------------- PTX helpers ----------------
__device__ __forceinline__ void cpa16(uint32_t dst, const void* src) {
    asm volatile("cp.async.ca.shared.global [%0], [%1], 16;" :: "r"(dst), "l"(src));
}
__device__ __forceinline__ void cpa8(uint32_t dst, const void* src) {
    asm volatile("cp.async.ca.shared.global [%0], [%1], 8;" :: "r"(dst), "l"(src));
}
__device__ __forceinline__ void ldsm4t(uint32_t& r0, uint32_t& r1,
                                       uint32_t& r2, uint32_t& r3, uint32_t a) {
    asm volatile("ldmatrix.sync.aligned.m8n8.x4.trans.shared.b16 {%0,%1,%2,%3}, [%4];"
                 : "=r"(r0), "=r"(r1), "=r"(r2), "=r"(r3) : "r"(a));
}
__device__ __forceinline__ void ldsm2t(uint32_t& r0, uint32_t& r1, uint32_t a) {
    asm volatile("ldmatrix.sync.aligned.m8n8.x2.trans.shared.b16 {%0,%1}, [%2];"
                 : "=r"(r0), "=r"(r1) : "r"(a));
}
__device__ __forceinline__ void mma16816(float* d, uint32_t a0, uint32_t a1,
                                         uint32_t a2, uint32_t a3,
                                         uint32_t b0, uint32_t b1) {
    asm volatile("mma.sync.aligned.m16n8k16.row.col.f32.f16.f16.f32 "
                 "{%0,%1,%2,%3}, {%4,%5,%6,%7}, {%8,%9}, {%0,%1,%2,%3};"
                 : "+f"(d[0]), "+f"(d[1]), "+f"(d[2]), "+f"(d[3])
                 : "r"(a0), "r"(a1), "r"(a2), "r"(a3), "r"(b0), "r"(b1));
}

// ---------------- main kernel ----------------
__global__ void __launch_bounds__(256, 1)
corr_mma(float* __restrict__ out) {
    extern __shared__ char smem[];
    const uint32_t sb = (uint32_t)__cvta_generic_to_shared(smem);
    const int tid = threadIdx.x;
    const int lane = tid & 31, warp = tid >> 5;   // warp = m16 block over w
    const int h = blockIdx.x, b = blockIdx.y;
    const size_t bbase = (size_t)b * NC * NH * NW;

    // Zero the f2 w-halos (padded cols 0-3 and 132-135) in all NBUF buffers;
    // cp.async only ever writes bytes [8, 264) of each 272B c-row.
    for (int i = tid; i < NBUF * 9 * 16; i += 256) {
        int buf = i / 144, rr = i % 144;
        char* row = smem + buf * BUFSZ + rr * RSTRIDE;
        *reinterpret_cast<uint64_t*>(row) = 0ull;        // halves 0-3
        *reinterpret_cast<uint64_t*>(row + 264) = 0ull;  // halves 132-135
    }
    __syncthreads();

    float acc[9][3][4];
    #pragma unroll
    for (int r = 0; r < 9; r++)
        #pragma unroll
        for (int t = 0; t < 3; t++)
            #pragma unroll
            for (int k = 0; k < 4; k++)
                acc[r][t][k] = 0.0f;

    // ldmatrix per-lane address components.
    // A (f1, stored [c][w]): x4 quads = (m0-7,k0-7),(m8-15,k0-7),(m0-7,k8-15),(m8-15,k8-15)
    const int q = lane >> 3, lrow = lane & 7;
    const uint32_t a_off = OFF_F1 + (uint32_t)(lrow + ((q >> 1) << 3)) * RSTRIDE
                         + ((16 * warp + ((q & 1) << 3)) << 1);
    // B (f2, stored [c][w'+4]): x2 quads = (k0-7,n0-7),(k8-15,n0-7): rows c = lane%16.
    const uint32_t b_row_off = (uint32_t)(lane & 15) * RSTRIDE;

    // cp.async task decomposition (per chunk):
    //   f2: 9r x 16c x 32 (8B segs)  = 4608 tasks -> 18/thread
    //   f1: 16c x 16 (16B segs)      =  256 tasks -> 1/thread
    auto issue = [&](int cc) {
        const int c0 = cc * 16;
        const uint32_t dbase = sb + (cc & (NBUF - 1)) * BUFSZ;
        #pragma unroll
        for (int s = 0; s < 18; s++) {
            int t = tid + 256 * s;
            int r = t >> 9, ci = (t >> 5) & 15, sg = t & 31;
            int gr = h + r - 4;
            gr = gr < 0 ? 0 : (gr > NH - 1 ? NH - 1 : gr);   // clamp; invalid di never stored
            const __half* src = g_f2h + bbase + ((size_t)(c0 + ci) * NH + gr) * NW + 4 * sg;
            cpa8(dbase + r * F2ROW + ci * RSTRIDE + 8 + 8 * sg, src);
        }
        {
            int ci = tid >> 4, sg = tid & 15;
            const __half* src = g_f1h + bbase + ((size_t)(c0 + ci) * NH + h) * NW + 8 * sg;
            cpa16(dbase + OFF_F1 + ci * RSTRIDE + 16 * sg, src);
        }
    };

    // prologue: 3 chunks in flight
    #pragma unroll
    for (int p = 0; p < 3; p++) {
        issue(p);
        asm volatile("cp.async.commit_group;");
    }

    for (int cc = 0; cc < 16; cc++) {
        // groups pending before wait = 3 + cc - cc = keep newest 2 -> chunk cc complete
        asm volatile("cp.async.wait_group 2;");
        __syncthreads();
        if (cc + 3 < 16) issue(cc + 3);          // buf (cc-1)&3: all consumers passed barrier
        asm volatile("cp.async.commit_group;");  // empty at tail keeps count uniform

        const uint32_t base = sb + (cc & (NBUF - 1)) * BUFSZ;
        uint32_t a0, a1, a2, a3;
        ldsm4t(a0, a1, a2, a3, base + a_off);
        #pragma unroll
        for (int r = 0; r < 9; r++) {
            const uint32_t brow = base + r * F2ROW + b_row_off + 32 * warp;
            #pragma unroll
            for (int t = 0; t < 3; t++) {
                uint32_t b0, b1;
                ldsm2t(b0, b1, brow + 16 * t);   // n8 tile at padded col 16*warp + 8*t
                mma16816(acc[r][t], a0, a1, a2, a3, b0, b1);
            }
        }
    }

    // ---------------- epilogue: band extraction via per-warp staging ----------------
    __syncthreads();   // all compute done before staging reuses nothing, but keep ordering clean
    float* stage = reinterpret_cast<float*>(smem + OFF_STAGE) + warp * 16 * STAGE_W;
    const int gid = lane >> 2, tig = lane & 3;
    const int l16 = lane & 15, dh = lane >> 4;
    #pragma unroll
    for (int r = 0; r < 9; r++) {
        #pragma unroll
        for (int t = 0; t < 3; t++) {
            stage[gid * STAGE_W + 8 * t + 2 * tig]           = acc[r][t][0];
            stage[gid * STAGE_W + 8 * t + 2 * tig + 1]       = acc[r][t][1];
            stage[(gid + 8) * STAGE_W + 8 * t + 2 * tig]     = acc[r][t][2];
            stage[(gid + 8) * STAGE_W + 8 * t + 2 * tig + 1] = acc[r][t][3];
        }
        __syncwarp();
        const int gr = h + r - 4;
        const bool valid = (gr >= 0 && gr < NH);
        // out[b, r*9+dj, h, 16*warp + l16] = band[l16][l16 + dj] (padded-col space)
        #pragma unroll
        for (int rd = 0; rd < 5; rd++) {
            int dj = 2 * rd + dh;
            if (dj < 9) {
                float v = valid ? stage[l16 * STAGE_W + l16 + dj] : 0.0f;
                out[(((size_t)b * ND + r * 9 + dj) * NH + h) * NW + 16 * warp + l16] = v;
            }
        }
        __syncwarp();
    }
}

extern "C" void kernel_launch(void* const* d_in, const int* in_sizes, int n_in,
                              void* d_out, int out_size) {
    const float* f1 = (const float*)d_in[0];
    const float* f2 = (const float*)d_in[1];
    float* out = (float*)d_out;

    cudaFuncSetAttribute(corr_mma, cudaFuncAttributeMaxDynamicSharedMemorySize, SMEM_SZ);

    cast_kernel<<<dim3(4096, 2), 256>>>((const float4*)f1, (const float4*)f2);
    corr_mma<<<dim3(NH, NB), 256, SMEM_SZ>>>(out);
}

// round 8
// speedup vs baseline: 1.2477x; 1.1057x over previous
#include <cuda_runtime.h>
#include <cuda_fp16.h>
#include <cstdint>

// Correlation layer via band-restricted mma.sync (m16n8k16 fp16, fp32 accum).
// out[b, di*9+dj, h, w] = sum_c f1[b,c,h,w] * f2[b,c,h+di-4,w+dj-4]
// B=8, C=256, H=64, W=128, D=81.
//
// R8: 512 threads / 16 warps: warp (m, half) computes m16 w-block m for
//     di rows 0-3 (half=0) or 4-8 (half=1)  -> 4 warps/SMSP latency hiding.
//     f1 is consumed fp32 directly (cp.async + in-reg cvt to A-fragments);
//     only f2 is pre-cast to fp16 (halves the cast pass).

#define NB 8
#define NC 256
#define NH 64
#define NW 128
#define ND 81

#define RSTRIDE 272                 // bytes per f2 c-row (136 halves; %128==16 -> LDSM conflict-free)
#define F2ROW (16 * RSTRIDE)        // one f2 row-block (16 c) = 4352 B
#define OFF_F1 (9 * F2ROW)          // 39168
#define F1STR 132                   // f1 fp32 row stride in words (528 B; banks 4*k+m distinct)
#define BUFSZ (OFF_F1 + 16 * F1STR * 4)   // 39168 + 8448 = 47616
#define NBUF 4
#define STAGE_W 25                  // floats per staging row
#define SMEM_SZ (NBUF * BUFSZ)      // 190464 B; epilogue staging aliases buffer 0

__device__ __half g_f2h[(size_t)NB * NC * NH * NW];

// ---------------- fp32 -> fp16 cast for f2 only ----------------
__global__ void cast_kernel(const float4* __restrict__ f2) {
    __half* dst = g_f2h;
    size_t i0 = (size_t)blockIdx.x * 1024 + threadIdx.x;
    #pragma unroll
    for (int k = 0; k < 4; k++) {
        size_t i = i0 + 256 * k;
        float4 v = f2[i];
        __half2 h0 = __floats2half2_rn(v.x, v.y);
        __half2 h1 = __floats2half2_rn(v.z, v.w);
        uint2 o;
        o.x = *reinterpret_cast<uint32_t*>(&h0);
        o.y = *reinterpret_cast<uint32_t*>(&h1);
        reinterpret_cast<uint2*>(dst)[i] = o;
    }
}

// ---------------- PTX helpers ----------------
__device__ __forceinline__ void cpa16(uint32_t dst, const void* src) {
    asm volatile("cp.async.ca.shared.global [%0], [%1], 16;" :: "r"(dst), "l"(src));
}
__device__ __forceinline__ void cpa8(uint32_t dst, const void* src) {
    asm volatile("cp.async.ca.shared.global [%0], [%1], 8;" :: "r"(dst), "l"(src));
}
__device__ __forceinline__ void ldsm2t(uint32_t& r0, uint32_t& r1, uint32_t a) {
    asm volatile("ldmatrix.sync.aligned.m8n8.x2.trans.shared.b16 {%0,%1}, [%2];"
                 : "=r"(r0), "=r"(r1) : "r"(a));
}
__device__ __forceinline__ void mma16816(float* d, uint32_t a0, uint32_t a1,
                                         uint32_t a2, uint32_t a3,
                                         uint32_t b0, uint32_t b1) {
    asm volatile("mma.sync.aligned.m16n8k16.row.col.f32.f16.f16.f32 "
                 "{%0,%1,%2,%3}, {%4,%5,%6,%7}, {%8,%9}, {%0,%1,%2,%3};"
                 : "+f"(d[0]), "+f"(d[1]), "+f"(d[2]), "+f"(d[3])
                 : "r"(a0), "r"(a1), "r"(a2), "r"(a3), "r"(b0), "r"(b1));
}
__device__ __forceinline__ uint32_t pkh2(float lo, float hi) {
    __half2 h = __floats2half2_rn(lo, hi);
    return *reinterpret_cast<uint32_t*>(&h);
}

// ---------------- main kernel ----------------
__global__ void __launch_bounds__(512, 1)
corr_mma(const float* __restrict__ f1, float* __restrict__ out) {
    extern __shared__ char smem[];
    const uint32_t sb = (uint32_t)__cvta_generic_to_shared(smem);
    const int tid = threadIdx.x;
    const int lane = tid & 31, warp = tid >> 5;
    const int m = warp >> 1, half = warp & 1;   // m16 block, r-half
    const int h = blockIdx.x, b = blockIdx.y;
    const size_t bbase = (size_t)b * NC * NH * NW;

    // Zero the f2 w-halos (padded cols 0-3 and 132-135) in all NBUF buffers.
    for (int i = tid; i < NBUF * 9 * 16; i += 512) {
        int buf = i / 144, rr = i % 144;
        char* row = smem + buf * BUFSZ + rr * RSTRIDE;
        *reinterpret_cast<uint64_t*>(row) = 0ull;
        *reinterpret_cast<uint64_t*>(row + 264) = 0ull;
    }
    __syncthreads();

    const int r0 = half ? 4 : 0;
    const int rn = half ? 5 : 4;

    float acc[5][3][4];
    #pragma unroll
    for (int ri = 0; ri < 5; ri++)
        #pragma unroll
        for (int t = 0; t < 3; t++)
            #pragma unroll
            for (int k = 0; k < 4; k++)
                acc[ri][t][k] = 0.0f;

    // A fragment source (f1 fp32 in smem, [k][m_global] with stride F1STR words).
    const int gid = lane >> 2, tig = lane & 3;
    const uint32_t a_word0 = (uint32_t)(2 * tig) * F1STR + 16 * m + gid;  // +mg
    // B (f2 fp16 [c][w'+4], .trans x2): rows c = lane%16.
    const uint32_t b_row_off = (uint32_t)(lane & 15) * RSTRIDE;

    // cp.async per chunk (512 threads):
    //   f2: 9r x 16c x 32 8B segs = 4608 tasks -> 9/thread
    //   f1 fp32: 16c x 32 16B segs = 512 tasks -> 1/thread
    auto issue = [&](int cc) {
        const int c0 = cc * 16;
        const uint32_t dbase = sb + (cc & (NBUF - 1)) * BUFSZ;
        #pragma unroll
        for (int s = 0; s < 9; s++) {
            int t = tid + 512 * s;
            int r = t >> 9, rem = t & 511;
            int ci = rem >> 5, sg = rem & 31;
            int gr = h + r - 4;
            gr = gr < 0 ? 0 : (gr > NH - 1 ? NH - 1 : gr);   // clamp; invalid di never stored
            const __half* src = g_f2h + bbase + ((size_t)(c0 + ci) * NH + gr) * NW + 4 * sg;
            cpa8(dbase + r * F2ROW + ci * RSTRIDE + 8 + 8 * sg, src);
        }
        {
            int ci = tid >> 5, sg = tid & 31;
            const float* src = f1 + bbase + ((size_t)(c0 + ci) * NH + h) * NW + 4 * sg;
            cpa16(dbase + OFF_F1 + ci * (F1STR * 4) + 16 * sg, src);
        }
    };

    #pragma unroll
    for (int p = 0; p < 3; p++) {
        issue(p);
        asm volatile("cp.async.commit_group;");
    }

    for (int cc = 0; cc < 16; cc++) {
        asm volatile("cp.async.wait_group 2;");
        __syncthreads();
        if (cc + 3 < 16) issue(cc + 3);
        asm volatile("cp.async.commit_group;");  // empty at tail keeps count uniform

        const uint32_t base = sb + (cc & (NBUF - 1)) * BUFSZ;
        // Build A fragments from fp32 f1: rows 2tig(+1), 2tig+8(+1); cols mg, mg+8.
        const float* fp = reinterpret_cast<const float*>(smem
                            + (cc & (NBUF - 1)) * BUFSZ + OFF_F1) + a_word0;
        uint32_t a0 = pkh2(fp[0],            fp[F1STR]);
        uint32_t a1 = pkh2(fp[8],            fp[F1STR + 8]);
        uint32_t a2 = pkh2(fp[8 * F1STR],    fp[9 * F1STR]);
        uint32_t a3 = pkh2(fp[8 * F1STR + 8], fp[9 * F1STR + 8]);

        #pragma unroll
        for (int ri = 0; ri < 5; ri++) {
            if (ri < rn) {
                const int r = r0 + ri;
                const uint32_t brow = base + r * F2ROW + b_row_off + 32 * m;
                #pragma unroll
                for (int t = 0; t < 3; t++) {
                    uint32_t b0, b1;
                    ldsm2t(b0, b1, brow + 16 * t);   // n8 tile at padded col 16m + 8t
                    mma16816(acc[ri][t], a0, a1, a2, a3, b0, b1);
                }
            }
        }
    }

    // ---------------- epilogue: band extraction via per-warp staging ----------------
    __syncthreads();   // buffers dead; staging aliases them
    float* stage = reinterpret_cast<float*>(smem) + warp * 16 * STAGE_W;
    const int l16 = lane & 15, dh = lane >> 4;
    #pragma unroll
    for (int ri = 0; ri < 5; ri++) {
        if (ri < rn) {
            const int r = r0 + ri;
            #pragma unroll
            for (int t = 0; t < 3; t++) {
                stage[gid * STAGE_W + 8 * t + 2 * tig]           = acc[ri][t][0];
                stage[gid * STAGE_W + 8 * t + 2 * tig + 1]       = acc[ri][t][1];
                stage[(gid + 8) * STAGE_W + 8 * t + 2 * tig]     = acc[ri][t][2];
                stage[(gid + 8) * STAGE_W + 8 * t + 2 * tig + 1] = acc[ri][t][3];
            }
            __syncwarp();
            const int gr = h + r - 4;
            const bool valid = (gr >= 0 && gr < NH);
            // out[b, r*9+dj, h, 16m + l16] = band[l16][l16 + dj] (padded-col space)
            #pragma unroll
            for (int rd = 0; rd < 5; rd++) {
                int dj = 2 * rd + dh;
                if (dj < 9) {
                    float v = valid ? stage[l16 * STAGE_W + l16 + dj] : 0.0f;
                    out[(((size_t)b * ND + r * 9 + dj) * NH + h) * NW + 16 * m + l16] = v;
                }
            }
            __syncwarp();
        }
    }
}

extern "C" void kernel_launch(void* const* d_in, const int* in_sizes, int n_in,
                              void* d_out, int out_size) {
    const float* f1 = (const float*)d_in[0];
    const float* f2 = (const float*)d_in[1];
    float* out = (float*)d_out;

    cudaFuncSetAttribute(corr_mma, cudaFuncAttributeMaxDynamicSharedMemorySize, SMEM_SZ);

    cast_kernel<<<4096, 256>>>((const float4*)f2);
    corr_mma<<<dim3(NH, NB), 512, SMEM_SZ>>>(f1, out);
}